// round 11
// baseline (speedup 1.0000x reference)
#include <cuda_runtime.h>
#include <cuda_bf16.h>
#include <math.h>
#include <stdint.h>

// ---------------- problem constants ----------------
#define BATCH 4
#define DM    192
#define DI    384
#define DS    16
#define DR    12
#define NSEQ  1024
#define LROWS 4096
#define NDIR  4
#define DBL_W 44

typedef __nv_bfloat16 bf16;

// ---------------- scratch ----------------
__device__ float g_xs  [LROWS*DM];
__device__ float g_dbl [NDIR*LROWS*DBL_W];
__device__ float g_h3  [LROWS*DM];
__device__ float g_cb  [DM];
__device__ float g_bz  [NDIR*2*DI];

__device__ bf16 g_xs_h  [LROWS*DM];
__device__ bf16 g_xz_h  [(long)NDIR*LROWS*2*DI];
__device__ bf16 g_xsm_h [NDIR*LROWS*DI];
__device__ bf16 g_y_h   [NDIR*LROWS*DI];
__device__ bf16 g_hdn_h [LROWS*2*DM];

__device__ bf16 g_w_inproj_h[NDIR*2*DI*DM];
__device__ bf16 g_w_xp_h    [NDIR*DBL_W*DI];
__device__ bf16 g_w_f1_h    [2*DM*4*DM];
__device__ bf16 g_w_inT     [DM*DM];           // Win^T
__device__ bf16 g_w_outT    [NDIR*DI*DM];      // Wout[d]^T
__device__ bf16 g_wz        [NDIR*2*DI*DM];    // Wm[d] @ Win
__device__ bf16 g_wc2       [NDIR*DI*DI];      // f_w1_slice_d @ Wout[d]
__device__ bf16 g_cw_h      [DM*2*DM];         // o_w @ f_w2

// ---------------- helpers ----------------
__device__ __forceinline__ float apply_act(float v, int act) {
    if (act == 1) {
        v = (v > 20.f) ? v : log1pf(__expf(v));
    } else if (act == 2) {
        v = 0.5f * v * (1.f + erff(v * 0.70710678118654752f));
    }
    return v;
}

__device__ __forceinline__ int seq_src_n(int d, int t) {
    if (d == 0) return t;
    if (d == 1) return NSEQ - 1 - t;
    if (d == 2) return ((t & 31) << 5) + (t >> 5);
    int u = NSEQ - 1 - t;
    return ((u & 31) << 5) + (u >> 5);
}

__device__ __forceinline__ void mma_bf16(float4& c,
    uint32_t a0, uint32_t a1, uint32_t a2, uint32_t a3, uint32_t b0, uint32_t b1) {
    asm volatile(
        "mma.sync.aligned.m16n8k16.row.col.f32.bf16.bf16.f32 "
        "{%0,%1,%2,%3}, {%4,%5,%6,%7}, {%8,%9}, {%0,%1,%2,%3};\n"
        : "+f"(c.x), "+f"(c.y), "+f"(c.z), "+f"(c.w)
        : "r"(a0), "r"(a1), "r"(a2), "r"(a3), "r"(b0), "r"(b1));
}

__device__ __forceinline__ void ldsm_x4(uint32_t addr,
    uint32_t& r0, uint32_t& r1, uint32_t& r2, uint32_t& r3) {
    asm volatile("ldmatrix.sync.aligned.m8n8.x4.shared.b16 {%0,%1,%2,%3}, [%4];"
        : "=r"(r0), "=r"(r1), "=r"(r2), "=r"(r3) : "r"(addr));
}

__device__ __forceinline__ uint32_t pack_bf2(float lo, float hi) {
    __nv_bfloat162 p = __floats2bfloat162_rn(lo, hi);
    return *(uint32_t*)&p;
}

__device__ __forceinline__ void cp16(uint32_t saddr, const void* gptr, int src_bytes) {
    asm volatile("cp.async.cg.shared.global [%0], [%1], 16, %2;\n"
        :: "r"(saddr), "l"(gptr), "r"(src_bytes));
}
__device__ __forceinline__ void cp_commit() {
    asm volatile("cp.async.commit_group;\n");
}
__device__ __forceinline__ void cp_wait2() { asm volatile("cp.async.wait_group 2;\n"); }
__device__ __forceinline__ void cp_wait1() { asm volatile("cp.async.wait_group 1;\n"); }
__device__ __forceinline__ void cp_wait0() { asm volatile("cp.async.wait_group 0;\n"); }

// exact-tail wait: guarantees stage kt complete before compute
__device__ __forceinline__ void cp_wait_stage(int kt, int nkt) {
    if (kt < nkt - 2) cp_wait2();
    else if (kt == nkt - 2) cp_wait1();
    else cp_wait0();
}

// ---------------- prep: conversions + transposes + combines ----------------
#define N_INP (NDIR*2*DI*DM)
#define N_XP  (NDIR*DBL_W*DI)
#define N_F1  (2*DM*4*DM)
#define N_WIT (DM*DM)
#define N_WOT (NDIR*DI*DM)
#define B_INP ((N_INP+255)/256)
#define B_XP  ((N_XP+255)/256)
#define B_F1  ((N_F1+255)/256)
#define B_WIT ((N_WIT+255)/256)
#define B_WOT ((N_WOT+255)/256)
#define B_CMB DM
#define B_BZ  ((NDIR*2*DI+255)/256)
#define B_TOTAL (B_INP+B_XP+B_F1+B_WIT+B_WOT+B_CMB+B_BZ)

__global__ __launch_bounds__(256) void prep_w_kernel(
    const float* in_w, const float* in_b, const float* m_in_w,
    const float* m_xp_w, const float* m_out_w, const float* f_w1,
    const float* o_w, const float* o_b, const float* f_w2, const float* f_b2)
{
    int blk = blockIdx.x;
    const int tid = threadIdx.x;
    if (blk < B_INP) {
        long i = (long)blk * 256 + tid;
        if (i < N_INP) g_w_inproj_h[i] = __float2bfloat16(m_in_w[i]);
        return;
    }
    blk -= B_INP;
    if (blk < B_XP) {
        long i = (long)blk * 256 + tid;
        if (i < N_XP) g_w_xp_h[i] = __float2bfloat16(m_xp_w[i]);
        return;
    }
    blk -= B_XP;
    if (blk < B_F1) {
        long i = (long)blk * 256 + tid;
        if (i < N_F1) g_w_f1_h[i] = __float2bfloat16(f_w1[i]);
        return;
    }
    blk -= B_F1;
    if (blk < B_WIT) {                          // Win^T: [k][j] = in_w[j][k]
        long i = (long)blk * 256 + tid;
        if (i < N_WIT) {
            int k = (int)(i / DM), j = (int)(i % DM);
            g_w_inT[i] = __float2bfloat16(in_w[j * DM + k]);
        }
        return;
    }
    blk -= B_WIT;
    if (blk < B_WOT) {                          // Wout[d]^T: [d][k][j] = m_out_w[d][j][k]
        long i = (long)blk * 256 + tid;
        if (i < N_WOT) {
            int d = (int)(i / (DI * DM));
            int r = (int)(i % (DI * DM));
            int k = r / DM, j = r % DM;
            g_w_outT[i] = __float2bfloat16(m_out_w[((long)d * DM + j) * DI + k]);
        }
        return;
    }
    blk -= B_WOT;
    if (blk < B_CMB) {                          // Wc = o_w @ f_w2, bc = o_w @ f_b2 + o_b
        const int i = blk;
        __shared__ float s_ow[DM];
        __shared__ float red[256];
        for (int j = tid; j < DM; j += 256) s_ow[j] = o_w[i * DM + j];
        __syncthreads();
        for (int k = tid; k < 2 * DM; k += 256) {
            float acc = 0.f;
            for (int j = 0; j < DM; j++)
                acc = fmaf(s_ow[j], f_w2[j * (2 * DM) + k], acc);
            g_cw_h[i * (2 * DM) + k] = __float2bfloat16(acc);
        }
        float pb = 0.f;
        for (int j = tid; j < DM; j += 256) pb = fmaf(s_ow[j], f_b2[j], pb);
        red[tid] = pb;
        __syncthreads();
        for (int st = 128; st > 0; st >>= 1) {
            if (tid < st) red[tid] += red[tid + st];
            __syncthreads();
        }
        if (tid == 0) g_cb[i] = red[0] + o_b[i];
        return;
    }
    blk -= B_CMB;
    {                                            // bz[d][n] = Wm[d][n,:] . in_b
        int row = blk * 256 + tid;
        if (row < NDIR * 2 * DI) {
            float acc = 0.f;
            const float* wr = m_in_w + (long)row * DM;
            for (int j = 0; j < DM; j++) acc = fmaf(wr[j], in_b[j], acc);
            g_bz[row] = acc;
        }
    }
}

// ---------------- bf16 cp.async GEMM, BK=32, NST=4, exact tail waits ----------------
// mode: 0 plain, 1 gather A rows via seq_src_n(z,.)
template<int MFRAG, int NFRAG>
__global__ __launch_bounds__(256) void gemm_bf16_kernel(
    const bf16* __restrict__ A, const bf16* __restrict__ W,
    const float* __restrict__ bias, void* __restrict__ Cv,
    int M, int Nn, int K, int lda, int ldc,
    long sA_, long sW_, long sB_, long sC_, int act, int mode, int cbf)
{
    constexpr int TM = MFRAG * 32;
    constexpr int TN = NFRAG * 32;
    constexpr int PITCH = 40;
    const int z = blockIdx.z;
    A += z * sA_; W += z * sW_;
    const float* bz = bias ? (bias + z * sB_) : (const float*)0;

    __shared__ __align__(16) bf16 sA[4][TM][PITCH];
    __shared__ __align__(16) bf16 sB[4][TN][PITCH];
    constexpr uint32_t A_ST = TM * PITCH * 2;
    constexpr uint32_t B_ST = TN * PITCH * 2;

    const int bm = blockIdx.y * TM, bn = blockIdx.x * TN;
    const int tid = threadIdx.x;

    constexpr int TPR_A = 256 / TM;
    constexpr int NCP_A = 4 / TPR_A;
    constexpr int TPR_B = 256 / TN;
    constexpr int NCP_B = 4 / TPR_B;

    const int rA = tid / TPR_A;
    const int kA = (tid % TPR_A) * (NCP_A * 8);
    long arowi;
    if (mode == 1) {
        int gm = bm + rA;
        arowi = (long)(((gm >> 10) << 10) + seq_src_n(z, gm & 1023));
    } else {
        arowi = bm + rA;
    }
    const bf16* aPtr = A + arowi * lda + kA;
    const int rB = tid / TPR_B;
    const int kB = (tid % TPR_B) * (NCP_B * 8);
    const int gw_n = bn + rB;
    const bool wv = (gw_n < Nn);
    const bf16* wPtr = W + (wv ? (long)gw_n * K : 0) + kB;

    const uint32_t aDst0 = (uint32_t)__cvta_generic_to_shared(&sA[0][rA][kA]);
    const uint32_t bDst0 = (uint32_t)__cvta_generic_to_shared(&sB[0][rB][kB]);

    const int nkt = K >> 5;

    auto issue = [&](int kt) {
        const int s = kt & 3;
#pragma unroll
        for (int q = 0; q < NCP_A; q++)
            cp16(aDst0 + s * A_ST + q * 16, aPtr + (kt << 5) + q * 8, 16);
#pragma unroll
        for (int q = 0; q < NCP_B; q++)
            cp16(bDst0 + s * B_ST + q * 16, wPtr + (kt << 5) + q * 8, wv ? 16 : 0);
        cp_commit();
    };

    issue(0); issue(1); issue(2);

    float4 acc[MFRAG][NFRAG];
#pragma unroll
    for (int i = 0; i < MFRAG; i++)
#pragma unroll
        for (int j = 0; j < NFRAG; j++) acc[i][j] = make_float4(0.f, 0.f, 0.f, 0.f);

    const int lane = tid & 31, wid = tid >> 5;
    const int wm = wid >> 2, wn = wid & 3;

    const int a_row = wm * (MFRAG * 16) + (lane & 7) + (((lane >> 3) & 1) << 3);
    const int a_kc  = (lane >> 4) << 3;
    const uint32_t aAddr0 = (uint32_t)__cvta_generic_to_shared(&sA[0][a_row][a_kc]);
    const int b_row = wn * (NFRAG * 8) + (lane & 7) + ((lane >> 4) << 3);
    const int b_kc  = ((lane >> 3) & 1) << 3;
    const uint32_t bAddr0 = (uint32_t)__cvta_generic_to_shared(&sB[0][b_row][b_kc]);

    for (int kt = 0; kt < nkt; kt++) {
        cp_wait_stage(kt, nkt);
        __syncthreads();
        if (kt + 3 < nkt) issue(kt + 3);

        const int s = kt & 3;
        const uint32_t aBase = aAddr0 + s * A_ST;
        const uint32_t bBase = bAddr0 + s * B_ST;
#pragma unroll
        for (int s2 = 0; s2 < 2; s2++) {
            const uint32_t aA = aBase + s2 * 32;
            const uint32_t bA = bBase + s2 * 32;
            uint32_t ra[MFRAG][4];
#pragma unroll
            for (int i = 0; i < MFRAG; i++)
                ldsm_x4(aA + i * (16 * PITCH * 2), ra[i][0], ra[i][1], ra[i][2], ra[i][3]);
            uint32_t rb[NFRAG][2];
#pragma unroll
            for (int jp = 0; jp < NFRAG / 2; jp++) {
                uint32_t b0, b1, b2, b3;
                ldsm_x4(bA + jp * (16 * PITCH * 2), b0, b1, b2, b3);
                rb[2 * jp][0] = b0; rb[2 * jp][1] = b1;
                rb[2 * jp + 1][0] = b2; rb[2 * jp + 1][1] = b3;
            }
#pragma unroll
            for (int i = 0; i < MFRAG; i++)
#pragma unroll
                for (int j = 0; j < NFRAG; j++)
                    mma_bf16(acc[i][j], ra[i][0], ra[i][1], ra[i][2], ra[i][3],
                             rb[j][0], rb[j][1]);
        }
    }

    // ---- epilogue ----
    const int row0 = lane >> 2;
    const int col0 = (lane & 3) << 1;
    float* Cf = (float*)Cv + z * sC_;
    bf16*  Ch = (bf16*)Cv + z * sC_;
#pragma unroll
    for (int i = 0; i < MFRAG; i++) {
        const int gmA = bm + wm * (MFRAG * 16) + (i << 4) + row0;
        const int gmB = gmA + 8;
#pragma unroll
        for (int j = 0; j < NFRAG; j++) {
            const int gn = bn + wn * (NFRAG * 8) + (j << 3) + col0;
            if (gn < Nn) {
                float4 v = acc[i][j];
                if (bz) {
                    const float b0 = bz[gn], b1 = bz[gn + 1];
                    v.x += b0; v.y += b1; v.z += b0; v.w += b1;
                }
                if (act) {
                    v.x = apply_act(v.x, act); v.y = apply_act(v.y, act);
                    v.z = apply_act(v.z, act); v.w = apply_act(v.w, act);
                }
                if (cbf) {
                    *(uint32_t*)&Ch[(long)gmA * ldc + gn] = pack_bf2(v.x, v.y);
                    *(uint32_t*)&Ch[(long)gmB * ldc + gn] = pack_bf2(v.z, v.w);
                } else {
                    *(float2*)&Cf[(long)gmA * ldc + gn] = make_float2(v.x, v.y);
                    *(float2*)&Cf[(long)gmB * ldc + gn] = make_float2(v.z, v.w);
                }
            }
        }
    }
}

// ---------------- merged out_proj + ffn1:  hdn = gelu(Σ_d gather_d(y[d]) @ Wc2[d]^T + b1) ----------------
// 64x64 tiles, accumulates over the 4 directions inside the kernel.
__global__ __launch_bounds__(256) void gemm_hdn_kernel(
    const bf16* __restrict__ Y, const bf16* __restrict__ WC,
    const float* __restrict__ bias, bf16* __restrict__ C)
{
    constexpr int TM = 64, TN = 64, PITCH = 40;
    __shared__ __align__(16) bf16 sA[4][TM][PITCH];
    __shared__ __align__(16) bf16 sB[4][TN][PITCH];
    constexpr uint32_t A_ST = TM * PITCH * 2;
    constexpr uint32_t B_ST = TN * PITCH * 2;

    const int bm = blockIdx.y * TM, bn = blockIdx.x * TN;
    const int tid = threadIdx.x;

    const int rr = tid >> 2;            // 0..63 row, 4 threads per row
    const int kk8 = (tid & 3) << 3;     // 0,8,16,24
    const int gm = bm + rr;
    const int gw_n = bn + rr;

    const uint32_t aDst0 = (uint32_t)__cvta_generic_to_shared(&sA[0][rr][kk8]);
    const uint32_t bDst0 = (uint32_t)__cvta_generic_to_shared(&sB[0][rr][kk8]);

    float4 acc[2][2];
#pragma unroll
    for (int i = 0; i < 2; i++)
#pragma unroll
        for (int j = 0; j < 2; j++) acc[i][j] = make_float4(0.f, 0.f, 0.f, 0.f);

    const int lane = tid & 31, wid = tid >> 5;
    const int wm = wid >> 2, wn = wid & 3;
    const int a_row = wm * 32 + (lane & 7) + (((lane >> 3) & 1) << 3);
    const int a_kc  = (lane >> 4) << 3;
    const uint32_t aAddr0 = (uint32_t)__cvta_generic_to_shared(&sA[0][a_row][a_kc]);
    const int b_row = wn * 16 + (lane & 7) + ((lane >> 4) << 3);
    const int b_kc  = ((lane >> 3) & 1) << 3;
    const uint32_t bAddr0 = (uint32_t)__cvta_generic_to_shared(&sB[0][b_row][b_kc]);

    constexpr int nkt = DI / 32;        // 12 per direction

    for (int d = 0; d < NDIR; d++) {
        const long arow = (long)d * LROWS + ((gm >> 10) << 10) + seq_src_n(d, gm & 1023);
        const bf16* aPtr = Y + arow * DI + kk8;
        const bf16* wPtr = WC + (long)d * DI * DI + (long)gw_n * DI + kk8;

        auto issue = [&](int kt) {
            const int s = kt & 3;
            cp16(aDst0 + s * A_ST, aPtr + (kt << 5), 16);
            cp16(bDst0 + s * B_ST, wPtr + (kt << 5), 16);
            cp_commit();
        };
        issue(0); issue(1); issue(2);

        for (int kt = 0; kt < nkt; kt++) {
            cp_wait_stage(kt, nkt);
            __syncthreads();
            if (kt + 3 < nkt) issue(kt + 3);

            const int s = kt & 3;
            const uint32_t aBase = aAddr0 + s * A_ST;
            const uint32_t bBase = bAddr0 + s * B_ST;
#pragma unroll
            for (int s2 = 0; s2 < 2; s2++) {
                const uint32_t aA = aBase + s2 * 32;
                const uint32_t bA = bBase + s2 * 32;
                uint32_t ra[2][4];
#pragma unroll
                for (int i = 0; i < 2; i++)
                    ldsm_x4(aA + i * (16 * PITCH * 2), ra[i][0], ra[i][1], ra[i][2], ra[i][3]);
                uint32_t b0, b1, b2, b3;
                ldsm_x4(bA, b0, b1, b2, b3);
#pragma unroll
                for (int i = 0; i < 2; i++) {
                    mma_bf16(acc[i][0], ra[i][0], ra[i][1], ra[i][2], ra[i][3], b0, b1);
                    mma_bf16(acc[i][1], ra[i][0], ra[i][1], ra[i][2], ra[i][3], b2, b3);
                }
            }
        }
    }

    // ---- epilogue: bias + gelu, bf16 out ----
    const int row0 = lane >> 2;
    const int col0 = (lane & 3) << 1;
#pragma unroll
    for (int i = 0; i < 2; i++) {
        const int gmA = bm + wm * 32 + (i << 4) + row0;
        const int gmB = gmA + 8;
#pragma unroll
        for (int j = 0; j < 2; j++) {
            const int gn = bn + wn * 16 + (j << 3) + col0;
            float4 v = acc[i][j];
            const float b0 = bias[gn], b1 = bias[gn + 1];
            v.x += b0; v.y += b1; v.z += b0; v.w += b1;
            v.x = apply_act(v.x, 2); v.y = apply_act(v.y, 2);
            v.z = apply_act(v.z, 2); v.w = apply_act(v.w, 2);
            *(uint32_t*)&C[(long)gmA * (2 * DM) + gn] = pack_bf2(v.x, v.y);
            *(uint32_t*)&C[(long)gmB * (2 * DM) + gn] = pack_bf2(v.z, v.w);
        }
    }
}

// ---------------- kernel 1: transpose + layernorm ----------------
__global__ __launch_bounds__(256) void ln1_kernel(
    const float* __restrict__ x, const float* __restrict__ g, const float* __restrict__ bb)
{
    __shared__ float tile[DM][33];
    __shared__ float s_mean[32], s_rstd[32];
    const int b = blockIdx.y, n0 = blockIdx.x << 5;
    const int tid = threadIdx.x;

    for (int i = tid; i < DM * 32; i += 256) {
        int d = i >> 5, nn = i & 31;
        tile[d][nn] = x[((long)(b * DM + d) << 10) + n0 + nn];
    }
    __syncthreads();

    const int nn = tid >> 3, l = tid & 7;
    float s = 0.f, s2 = 0.f;
    for (int d = l; d < DM; d += 8) { float v = tile[d][nn]; s += v; s2 = fmaf(v, v, s2); }
    s  += __shfl_down_sync(0xffffffffu, s,  4, 8);
    s2 += __shfl_down_sync(0xffffffffu, s2, 4, 8);
    s  += __shfl_down_sync(0xffffffffu, s,  2, 8);
    s2 += __shfl_down_sync(0xffffffffu, s2, 2, 8);
    s  += __shfl_down_sync(0xffffffffu, s,  1, 8);
    s2 += __shfl_down_sync(0xffffffffu, s2, 1, 8);
    if (l == 0) {
        float m = s * (1.f / DM);
        float var = s2 * (1.f / DM) - m * m;
        s_mean[nn] = m;
        s_rstd[nn] = rsqrtf(var + 1e-5f);
    }
    __syncthreads();

    for (int i = tid; i < DM * 32; i += 256) {
        int nn2 = i / DM, d = i % DM;
        float v = (tile[d][nn2] - s_mean[nn2]) * s_rstd[nn2] * g[d] + bb[d];
        long adr = ((long)(b << 10) + n0 + nn2) * DM + d;
        g_xs[adr] = v;
        g_xs_h[adr] = __float2bfloat16(v);
    }
}

// ---------------- causal depthwise conv (width 4) + silu ----------------
__global__ __launch_bounds__(256) void conv_silu_kernel(
    const float* __restrict__ cw, const float* __restrict__ cb)
{
    const int gi = blockIdx.x * 256 + threadIdx.x;
    const int c = gi % DI;
    const int rest = gi / DI;
    const int tb = rest & 63;
    const int db = rest >> 6;
    const int d = db >> 2;
    const int t0 = tb << 4;

    const float* w = cw + ((long)d * DI + c) * 4;
    const float w0 = w[0], w1 = w[1], w2 = w[2], w3 = w[3];
    const float bias = cb[d * DI + c];
    const bf16* src = g_xz_h + ((long)db * NSEQ) * (2 * DI) + c;
    bf16* dst = g_xsm_h + ((long)db * NSEQ) * DI + c;

    float r0 = (t0 >= 3) ? __bfloat162float(src[(long)(t0 - 3) * (2 * DI)]) : 0.f;
    float r1 = (t0 >= 2) ? __bfloat162float(src[(long)(t0 - 2) * (2 * DI)]) : 0.f;
    float r2 = (t0 >= 1) ? __bfloat162float(src[(long)(t0 - 1) * (2 * DI)]) : 0.f;
#pragma unroll
    for (int i = 0; i < 16; i++) {
        const int t = t0 + i;
        const float cur = __bfloat162float(src[(long)t * (2 * DI)]);
        float a = bias;
        a = fmaf(w0, r0, a);
        a = fmaf(w1, r1, a);
        a = fmaf(w2, r2, a);
        a = fmaf(w3, cur, a);
        dst[(long)t * DI] = __float2bfloat16(a / (1.f + __expf(-a)));
        r0 = r1; r1 = r2; r2 = cur;
    }
}

// ---------------- selective scan with fused dt-projection ----------------
#define SCH 16
__global__ __launch_bounds__(256) void scan_kernel(
    const float* __restrict__ Alog, const float* __restrict__ Dp,
    const float* __restrict__ Wdt, const float* __restrict__ bdt)
{
    const int d = blockIdx.z, b = blockIdx.y;
    const int c0 = blockIdx.x << 6;
    const int tid = threadIdx.x;
    const int cl = tid >> 2;
    const int sg = tid & 3;
    const int c = c0 + cl;
    const long baseI = ((long)d * BATCH + b) * NSEQ;

    const bf16* xb   = g_xsm_h + baseI * DI       + c0;
    const bf16* zb   = g_xz_h  + baseI * (2 * DI) + DI + c0;
    const float* dblp = g_dbl + baseI * DBL_W;
    bf16* yb          = g_y_h + baseI * DI        + c0;

    __shared__ float s_wdt[64 * 13];
    __shared__ float s_bdt[64];
    __shared__ float s_raw[SCH * 12];
    __shared__ float s_bc [SCH * 32];
    __shared__ float s_dt [SCH * 64];
    __shared__ float s_x  [SCH * 64];
    __shared__ float s_g  [SCH * 64];

    for (int i = tid; i < 64 * DR; i += 256)
        s_wdt[(i / DR) * 13 + (i % DR)] = Wdt[((long)(d * DI + c0) + i / DR) * DR + (i % DR)];
    if (tid < 64) s_bdt[tid] = bdt[d * DI + c0 + tid];

    const float LOG2E = 1.44269504088896340736f;
    float Aa[4];
#pragma unroll
    for (int s = 0; s < 4; s++)
        Aa[s] = -expf(Alog[((long)(d * DI + c)) * DS + (sg << 2) + s]) * LOG2E;
    const float Dv = Dp[d * DI + c];

    float h[4];
#pragma unroll
    for (int s = 0; s < 4; s++) h[s] = 0.f;

    __syncthreads();

    for (int t0 = 0; t0 < NSEQ; t0 += SCH) {
        __syncthreads();
        if (tid < SCH * DR) s_raw[tid] = dblp[(long)(t0 + tid / DR) * DBL_W + (tid % DR)];
#pragma unroll
        for (int k = 0; k < 2; k++) {
            const int idx = tid + (k << 8);
            const int row = idx >> 5, col = idx & 31;
            s_bc[idx] = dblp[(long)(t0 + row) * DBL_W + DR + col];
        }
#pragma unroll
        for (int k = 0; k < 4; k++) {
            const int idx = tid + (k << 8);
            const int row = idx >> 6, col = idx & 63;
            s_x[idx] = __bfloat162float(xb[(long)(t0 + row) * DI + col]);
            const float zv = __bfloat162float(zb[(long)(t0 + row) * (2 * DI) + col]);
            s_g[idx] = zv / (1.f + __expf(-zv));
        }
        __syncthreads();
#pragma unroll
        for (int k = 0; k < 4; k++) {
            const int idx = tid + (k << 8);
            const int row = idx >> 6, col = idx & 63;
            float v = s_bdt[col];
#pragma unroll
            for (int j = 0; j < DR; j++)
                v = fmaf(s_raw[row * DR + j], s_wdt[col * 13 + j], v);
            s_dt[idx] = (v > 20.f) ? v : log1pf(__expf(v));
        }
        __syncthreads();

#pragma unroll
        for (int tt = 0; tt < SCH; tt++) {
            const float dt_v = s_dt[(tt << 6) + cl];
            const float x_v  = s_x [(tt << 6) + cl];
            const float* bc = s_bc + (tt << 5);
            const float dtx = dt_v * x_v;
            float accv = 0.f;
#pragma unroll
            for (int s = 0; s < 4; s++) {
                const float dA = exp2f(dt_v * Aa[s]);
                h[s] = fmaf(dA, h[s], dtx * bc[(sg << 2) + s]);
                accv = fmaf(h[s], bc[16 + (sg << 2) + s], accv);
            }
            accv += __shfl_down_sync(0xffffffffu, accv, 2, 4);
            accv += __shfl_down_sync(0xffffffffu, accv, 1, 4);
            if (sg == 0) {
                float yv = fmaf(x_v, Dv, accv);
                yv *= s_g[(tt << 6) + cl];
                yb[(long)(t0 + tt) * DI + cl] = __float2bfloat16(yv);
            }
        }
    }
}

// ---------------- final layernorm + residual + transpose-out ----------------
__global__ __launch_bounds__(256) void ln2_kernel(
    const float* __restrict__ g, const float* __restrict__ bb, float* __restrict__ out)
{
    __shared__ float t1[16][193];
    __shared__ float t2[16][193];
    __shared__ float s_mean[16], s_rstd[16];
    const int b = blockIdx.y, n0 = blockIdx.x << 4;
    const int tid = threadIdx.x;

    for (int i = tid; i < 16 * DM; i += 256) {
        int nn = i / DM, dd = i % DM;
        long adr = ((long)(b << 10) + n0 + nn) * DM + dd;
        t1[nn][dd] = g_h3[adr];
        t2[nn][dd] = g_xs[adr];
    }
    __syncthreads();

    const int nn = tid >> 4, l = tid & 15;
    float s = 0.f, s2 = 0.f;
    for (int dd = l; dd < DM; dd += 16) { float v = t1[nn][dd]; s += v; s2 = fmaf(v, v, s2); }
    s  += __shfl_down_sync(0xffffffffu, s,  8, 16);
    s2 += __shfl_down_sync(0xffffffffu, s2, 8, 16);
    s  += __shfl_down_sync(0xffffffffu, s,  4, 16);
    s2 += __shfl_down_sync(0xffffffffu, s2, 4, 16);
    s  += __shfl_down_sync(0xffffffffu, s,  2, 16);
    s2 += __shfl_down_sync(0xffffffffu, s2, 2, 16);
    s  += __shfl_down_sync(0xffffffffu, s,  1, 16);
    s2 += __shfl_down_sync(0xffffffffu, s2, 1, 16);
    if (l == 0) {
        float m = s * (1.f / DM);
        float var = s2 * (1.f / DM) - m * m;
        s_mean[nn] = m;
        s_rstd[nn] = rsqrtf(var + 1e-5f);
    }
    __syncthreads();

    for (int i = tid; i < DM * 16; i += 256) {
        int dd = i >> 4, nn2 = i & 15;
        float v = (t1[nn2][dd] - s_mean[nn2]) * s_rstd[nn2] * g[dd] + bb[dd] + t2[nn2][dd];
        out[((long)(b * DM + dd) << 10) + n0 + nn2] = v;
    }
}

// ---------------- launcher ----------------
extern "C" void kernel_launch(void* const* d_in, const int* in_sizes, int n_in,
                              void* d_out, int out_size)
{
    const float* x        = (const float*)d_in[0];
    const float* norm_g   = (const float*)d_in[1];
    const float* norm_b   = (const float*)d_in[2];
    const float* in_w     = (const float*)d_in[3];
    const float* in_b     = (const float*)d_in[4];
    const float* m_in_w   = (const float*)d_in[5];
    const float* m_conv_w = (const float*)d_in[6];
    const float* m_conv_b = (const float*)d_in[7];
    const float* m_xp_w   = (const float*)d_in[8];
    const float* m_dt_w   = (const float*)d_in[9];
    const float* m_dt_b   = (const float*)d_in[10];
    const float* m_Alog   = (const float*)d_in[11];
    const float* m_D      = (const float*)d_in[12];
    const float* m_out_w  = (const float*)d_in[13];
    const float* f_w1     = (const float*)d_in[14];
    const float* f_b1     = (const float*)d_in[15];
    const float* f_w2     = (const float*)d_in[16];
    const float* f_b2     = (const float*)d_in[17];
    const float* o_w      = (const float*)d_in[18];
    const float* o_b      = (const float*)d_in[19];
    const float* on_g     = (const float*)d_in[20];
    const float* on_b     = (const float*)d_in[21];
    float* out = (float*)d_out;

    float *p_dbl, *p_h3, *p_cb, *p_bz;
    bf16 *p_xs_h, *p_xz_h, *p_xsm_h, *p_y_h, *p_hdn_h;
    bf16 *p_w_inproj, *p_w_xp, *p_w_f1, *p_w_inT, *p_w_outT, *p_wz, *p_wc2, *p_cw_h;
    cudaGetSymbolAddress((void**)&p_dbl, g_dbl);
    cudaGetSymbolAddress((void**)&p_h3, g_h3);
    cudaGetSymbolAddress((void**)&p_cb, g_cb);
    cudaGetSymbolAddress((void**)&p_bz, g_bz);
    cudaGetSymbolAddress((void**)&p_xs_h, g_xs_h);
    cudaGetSymbolAddress((void**)&p_xz_h, g_xz_h);
    cudaGetSymbolAddress((void**)&p_xsm_h, g_xsm_h);
    cudaGetSymbolAddress((void**)&p_y_h, g_y_h);
    cudaGetSymbolAddress((void**)&p_hdn_h, g_hdn_h);
    cudaGetSymbolAddress((void**)&p_w_inproj, g_w_inproj_h);
    cudaGetSymbolAddress((void**)&p_w_xp, g_w_xp_h);
    cudaGetSymbolAddress((void**)&p_w_f1, g_w_f1_h);
    cudaGetSymbolAddress((void**)&p_w_inT, g_w_inT);
    cudaGetSymbolAddress((void**)&p_w_outT, g_w_outT);
    cudaGetSymbolAddress((void**)&p_wz, g_wz);
    cudaGetSymbolAddress((void**)&p_wc2, g_wc2);
    cudaGetSymbolAddress((void**)&p_cw_h, g_cw_h);

    // 1) layernorm + transpose
    ln1_kernel<<<dim3(32, 4), 256>>>(x, norm_g, norm_b);

    // 2) weight prep: conversions, transposes, o/f2 combine, bz
    prep_w_kernel<<<B_TOTAL, 256>>>(in_w, in_b, m_in_w, m_xp_w, m_out_w, f_w1,
                                    o_w, o_b, f_w2, f_b2);

    // 3) Wz[d] = Wm[d] @ Win  (768 x 192 x 192, z=4)
    gemm_bf16_kernel<2, 2><<<dim3(3, 12, 4), 256>>>(p_w_inproj, p_w_inT, nullptr, p_wz,
        768, DM, DM, DM, DM,
        (long)768 * DM, 0, 0, (long)768 * DM, 0, 0, 1);

    // 4) xz[d] = gather_d(xs) @ Wz[d]^T + bz[d]   (captured by ncu)
    gemm_bf16_kernel<4, 4><<<dim3(6, 32, 4), 256>>>(p_xs_h, p_wz, p_bz, p_xz_h,
        LROWS, 2 * DI, DM, DM, 2 * DI,
        0, (long)2 * DI * DM, 2 * DI, (long)LROWS * 2 * DI, 0, 1, 1);

    // 5) causal depthwise conv + silu
    conv_silu_kernel<<<1536, 256>>>(m_conv_w, m_conv_b);

    // 6) Wc2[d] = f_w1[:, d*192:(d+1)*192] @ Wout[d]  (384 x 384 x 192, z=4)
    gemm_bf16_kernel<2, 2><<<dim3(6, 6, 4), 256>>>(p_w_f1, p_w_outT, nullptr, p_wc2,
        DI, DI, DM, 4 * DM, DI,
        (long)DM, (long)DI * DM, 0, (long)DI * DI, 0, 0, 1);

    // 7) dbl[d] = xsm[d] @ m_xp_w[d]^T
    gemm_bf16_kernel<2, 2><<<dim3(1, 64, 4), 256>>>(p_xsm_h, p_w_xp, nullptr, p_dbl,
        LROWS, DBL_W, DI, DI, DBL_W,
        (long)LROWS * DI, (long)DBL_W * DI, 0, (long)LROWS * DBL_W, 0, 0, 0);

    // 8) selective scan
    scan_kernel<<<dim3(6, BATCH, NDIR), 256>>>(m_Alog, m_D, m_dt_w, m_dt_b);

    // 9) hdn = gelu(Σ_d gather_d(y[d]) @ Wc2[d]^T + f_b1)  (merged out_proj + ffn1)
    gemm_hdn_kernel<<<dim3(6, 64), 256>>>(p_y_h, p_wc2, f_b1, p_hdn_h);

    // 10) h3 = hdn @ Wc^T + bc
    gemm_bf16_kernel<2, 2><<<dim3(3, 64, 1), 256>>>(p_hdn_h, p_cw_h, p_cb, p_h3,
        LROWS, DM, 2 * DM, 2 * DM, DM, 0, 0, 0, 0, 0, 0, 0);

    // 11) final layernorm + residual + transpose out
    ln2_kernel<<<dim3(64, 4), 256>>>(on_g, on_b, out);
}